// round 1
// baseline (speedup 1.0000x reference)
#include <cuda_runtime.h>
#include <cstdint>

#define D_IN 1024
#define HID  256
#define G4   1024
#define MID  512
#define SEQ  512
#define NB   4
#define NOUT 50
#define SED  64
#define NPOS 30
#define WLD  1090           // 2*(MID+1) + SED
#define ROWS 2048           // NB*SEQ
#define CPG  16             // CTAs per recurrence group
#define NGRP 8              // 2 dirs * 4 batch

// ------------------------- scratch (static device memory) -------------------
__device__ float g_G[2][ROWS][G4];      // gate input preactivations (+bias)
__device__ float g_bias[2][G4];
__device__ float g_hcat[ROWS][MID];     // [b*SEQ+t][dir*HID + j]
__device__ float g_head[ROWS][MID];
__device__ float g_tail[ROWS][MID];
__device__ float g_shead[ROWS][NOUT];   // [(b,m)][k]
__device__ float g_stail[ROWS][NOUT];   // [(b,n)][k]
__device__ float g_sztab[NOUT][NPOS];
__device__ float g_hbuf[2][NGRP][HID];  // double-buffered h
__device__ int   g_cnt[NGRP];

// ------------------------- prep: counters, bias, size table -----------------
__global__ void prep_kernel(const float* __restrict__ bih_f, const float* __restrict__ bhh_f,
                            const float* __restrict__ bih_b, const float* __restrict__ bhh_b,
                            const float* __restrict__ emb,   const float* __restrict__ W)
{
    int g = blockIdx.x * blockDim.x + threadIdx.x;
    if (g < NGRP) g_cnt[g] = 0;
    if (g < G4)            g_bias[0][g]      = bih_f[g]      + bhh_f[g];
    else if (g < 2 * G4)   g_bias[1][g - G4] = bih_b[g - G4] + bhh_b[g - G4];
    if (g < NOUT * NPOS) {
        int k = g / NPOS, p = g % NPOS;
        float s = 0.f;
        #pragma unroll 8
        for (int h = 0; h < SED; h++)
            s += emb[p * SED + h] * W[k * WLD + 2 * (MID + 1) + h];
        g_sztab[k][p] = s;
    }
}

// ------------------------- tf32 GEMM: C = A @ B^T (+bias, opt leaky) --------
// A: [2048 x K] row-major (lda), Bw: [N x K] row-major (ldb), C: [2048 x N] (ldc)
__device__ __forceinline__ float to_tf32(float x) {
    uint32_t u;
    asm("cvt.rna.tf32.f32 %0, %1;" : "=r"(u) : "f"(x));
    return __uint_as_float(u);
}

__global__ void __launch_bounds__(128) gemm_tf32(
    const float* __restrict__ A, int lda,
    const float* __restrict__ Bw, int ldb,
    const float* __restrict__ bias, int bstr,
    float* __restrict__ C, int ldc,
    int N, int K, int act)
{
    __shared__ float As[64][33];
    __shared__ float Bs[64][33];
    int tid  = threadIdx.x;
    int warp = tid >> 5, lane = tid & 31;
    int gq = lane >> 2, tg = lane & 3;
    int wm = (warp >> 1) * 32, wn = (warp & 1) * 32;
    int bm = blockIdx.y * 64, bn = blockIdx.x * 64;

    float acc[2][4][4];
    #pragma unroll
    for (int a = 0; a < 2; a++)
        #pragma unroll
        for (int b = 0; b < 4; b++)
            #pragma unroll
            for (int c = 0; c < 4; c++) acc[a][b][c] = 0.f;

    bool bvec = ((ldb & 3) == 0);

    for (int k0 = 0; k0 < K; k0 += 32) {
        #pragma unroll
        for (int i = 0; i < 4; i++) {
            int l4 = tid + i * 128;
            int r = l4 >> 3, c4 = (l4 & 7) << 2;
            const float4 v = *reinterpret_cast<const float4*>(A + (size_t)(bm + r) * lda + k0 + c4);
            As[r][c4 + 0] = to_tf32(v.x); As[r][c4 + 1] = to_tf32(v.y);
            As[r][c4 + 2] = to_tf32(v.z); As[r][c4 + 3] = to_tf32(v.w);
        }
        #pragma unroll
        for (int i = 0; i < 4; i++) {
            int l4 = tid + i * 128;
            int r = l4 >> 3, c4 = (l4 & 7) << 2;
            float4 v;
            if (bn + r < N) {
                if (bvec) {
                    v = *reinterpret_cast<const float4*>(Bw + (size_t)(bn + r) * ldb + k0 + c4);
                } else {
                    const float* p = Bw + (size_t)(bn + r) * ldb + k0 + c4;
                    v = make_float4(p[0], p[1], p[2], p[3]);
                }
            } else v = make_float4(0.f, 0.f, 0.f, 0.f);
            Bs[r][c4 + 0] = to_tf32(v.x); Bs[r][c4 + 1] = to_tf32(v.y);
            Bs[r][c4 + 2] = to_tf32(v.z); Bs[r][c4 + 3] = to_tf32(v.w);
        }
        __syncthreads();

        #pragma unroll
        for (int kk = 0; kk < 32; kk += 8) {
            uint32_t af[2][4], bf[4][2];
            #pragma unroll
            for (int mf = 0; mf < 2; mf++) {
                int r0 = wm + mf * 16 + gq;
                af[mf][0] = __float_as_uint(As[r0    ][kk + tg]);
                af[mf][1] = __float_as_uint(As[r0 + 8][kk + tg]);
                af[mf][2] = __float_as_uint(As[r0    ][kk + tg + 4]);
                af[mf][3] = __float_as_uint(As[r0 + 8][kk + tg + 4]);
            }
            #pragma unroll
            for (int nf = 0; nf < 4; nf++) {
                int n0 = wn + nf * 8 + gq;
                bf[nf][0] = __float_as_uint(Bs[n0][kk + tg]);
                bf[nf][1] = __float_as_uint(Bs[n0][kk + tg + 4]);
            }
            #pragma unroll
            for (int mf = 0; mf < 2; mf++)
                #pragma unroll
                for (int nf = 0; nf < 4; nf++)
                    asm volatile(
                        "mma.sync.aligned.m16n8k8.row.col.f32.tf32.tf32.f32 "
                        "{%0,%1,%2,%3}, {%4,%5,%6,%7}, {%8,%9}, {%0,%1,%2,%3};\n"
                        : "+f"(acc[mf][nf][0]), "+f"(acc[mf][nf][1]),
                          "+f"(acc[mf][nf][2]), "+f"(acc[mf][nf][3])
                        : "r"(af[mf][0]), "r"(af[mf][1]), "r"(af[mf][2]), "r"(af[mf][3]),
                          "r"(bf[nf][0]), "r"(bf[nf][1]));
        }
        __syncthreads();
    }

    #pragma unroll
    for (int mf = 0; mf < 2; mf++) {
        #pragma unroll
        for (int nf = 0; nf < 4; nf++) {
            int row = bm + wm + mf * 16 + gq;
            int col = bn + wn + nf * 8 + tg * 2;
            #pragma unroll
            for (int q = 0; q < 4; q++) {
                int r = row + (q >> 1) * 8;
                int c = col + (q & 1);
                if (c < N) {
                    float v = acc[mf][nf][q] + (bias ? bias[(size_t)c * bstr] : 0.f);
                    if (act) v = v > 0.f ? v : 0.01f * v;
                    C[(size_t)r * ldc + c] = v;
                }
            }
        }
    }
}

// ------------------------- LSTM recurrence ----------------------------------
// 8 groups (dir,batch) x 16 CTAs; each CTA owns 16 hidden units (64 gate rows).
// 512 threads: thread = (local_row lr in [0,64)) x (k-segment seg in [0,8)).
__device__ __forceinline__ float sigm(float x) { return 1.f / (1.f + __expf(-x)); }

__global__ void __launch_bounds__(512) lstm_kernel(const float* __restrict__ Whh_f,
                                                   const float* __restrict__ Whh_b)
{
    int grp = blockIdx.x / CPG;
    int cig = blockIdx.x % CPG;
    int d = grp >> 2, b = grp & 3;
    int tid = threadIdx.x;
    int lr = tid >> 3, seg = tid & 7;
    int gi = lr >> 4, lu = lr & 15;
    int j = cig * 16 + lu;
    int grow = gi * HID + j;
    const float* Whh = d ? Whh_b : Whh_f;

    float w[32];
    #pragma unroll
    for (int q = 0; q < 32; q++) w[q] = __ldg(&Whh[grow * HID + seg * 32 + q]);

    __shared__ float hs[HID];    // transposed: element (seg*32+q) stored at q*8+seg
    __shared__ float gsm[64];
    const float* Gd = &g_G[d][0][0];
    float cst = 0.f;

    for (int st = 0; st < SEQ; st++) {
        int t = d ? (SEQ - 1 - st) : st;
        if (st > 0) {
            if (tid == 0) {
                int tgt = CPG * st;
                volatile int* pc = &g_cnt[grp];
                while (*pc < tgt) { }
            }
            __syncthreads();
            if (tid < HID) {
                float hv = __ldcg(&g_hbuf[st & 1][grp][tid]);
                hs[(tid & 31) * 8 + (tid >> 5)] = hv;   // transpose for bank-free reads
            }
        } else {
            if (tid < HID) hs[tid] = 0.f;
        }
        __syncthreads();

        float gin = (seg == 0) ? __ldg(&Gd[(size_t)(b * SEQ + t) * G4 + grow]) : 0.f;

        float acc = 0.f;
        #pragma unroll
        for (int q = 0; q < 32; q++) acc += w[q] * hs[q * 8 + seg];
        acc += __shfl_down_sync(0xffffffffu, acc, 4, 8);
        acc += __shfl_down_sync(0xffffffffu, acc, 2, 8);
        acc += __shfl_down_sync(0xffffffffu, acc, 1, 8);

        if (seg == 0) {
            float x = acc + gin;
            gsm[lr] = (gi == 2) ? tanhf(x) : sigm(x);
        }
        __syncthreads();

        if (tid < 16) {
            float iv = gsm[tid], fv = gsm[16 + tid], gv = gsm[32 + tid], ov = gsm[48 + tid];
            cst = fv * cst + iv * gv;
            float h = ov * tanhf(cst);
            g_hbuf[(st + 1) & 1][grp][cig * 16 + tid] = h;
            g_hcat[b * SEQ + t][d * HID + cig * 16 + tid] = h;
            __threadfence();
        }
        __syncthreads();
        if (tid == 0) atomicAdd(&g_cnt[grp], 1);
    }
}

// ------------------------- final assembly -----------------------------------
// out[b][k][m][n] = s_head[b,k,m] + s_tail[b,k,n] + sztab[k][clamp(n-m)]
__global__ void __launch_bounds__(256) assemble_kernel(float* __restrict__ out)
{
    int b = blockIdx.z, k = blockIdx.y, m0 = blockIdx.x * 16;
    int tid = threadIdx.x;
    __shared__ float st_s[SEQ];
    __shared__ float sz_s[NPOS];
    __shared__ float sh_s[16];
    for (int i = tid; i < SEQ; i += 256) st_s[i] = g_stail[b * SEQ + i][k];
    if (tid < NPOS) sz_s[tid] = g_sztab[k][tid];
    if (tid < 16)   sh_s[tid] = g_shead[b * SEQ + m0 + tid][k];
    __syncthreads();

    float* orow = out + (((size_t)(b * NOUT + k)) * SEQ + m0) * SEQ;
    #pragma unroll
    for (int it = 0; it < 8; it++) {
        int lin = it * 256 + tid;
        int r = lin >> 7;
        int n4 = (lin & 127) << 2;
        int m = m0 + r;
        float sh = sh_s[r];
        float4 v;
        int e;
        e = min(max(n4     - m, -15), 14) + 15; v.x = sh + st_s[n4    ] + sz_s[e];
        e = min(max(n4 + 1 - m, -15), 14) + 15; v.y = sh + st_s[n4 + 1] + sz_s[e];
        e = min(max(n4 + 2 - m, -15), 14) + 15; v.z = sh + st_s[n4 + 2] + sz_s[e];
        e = min(max(n4 + 3 - m, -15), 14) + 15; v.w = sh + st_s[n4 + 3] + sz_s[e];
        *reinterpret_cast<float4*>(orow + (size_t)r * SEQ + n4) = v;
    }
}

// ------------------------- launch -------------------------------------------
extern "C" void kernel_launch(void* const* d_in, const int* in_sizes, int n_in,
                              void* d_out, int out_size)
{
    const float* x      = (const float*)d_in[0];
    const float* Wih_f  = (const float*)d_in[1];
    const float* Whh_f  = (const float*)d_in[2];
    const float* bih_f  = (const float*)d_in[3];
    const float* bhh_f  = (const float*)d_in[4];
    const float* Wih_b  = (const float*)d_in[5];
    const float* Whh_b  = (const float*)d_in[6];
    const float* bih_b  = (const float*)d_in[7];
    const float* bhh_b  = (const float*)d_in[8];
    const float* W_head = (const float*)d_in[9];
    const float* b_head = (const float*)d_in[10];
    const float* W_tail = (const float*)d_in[11];
    const float* b_tail = (const float*)d_in[12];
    const float* emb    = (const float*)d_in[13];
    const float* W      = (const float*)d_in[14];
    float* out = (float*)d_out;

    float *pG, *pBias, *pHcat, *pHead, *pTail, *pShead, *pStail;
    cudaGetSymbolAddress((void**)&pG,     g_G);
    cudaGetSymbolAddress((void**)&pBias,  g_bias);
    cudaGetSymbolAddress((void**)&pHcat,  g_hcat);
    cudaGetSymbolAddress((void**)&pHead,  g_head);
    cudaGetSymbolAddress((void**)&pTail,  g_tail);
    cudaGetSymbolAddress((void**)&pShead, g_shead);
    cudaGetSymbolAddress((void**)&pStail, g_stail);

    prep_kernel<<<8, 256>>>(bih_f, bhh_f, bih_b, bhh_b, emb, W);

    // Stage 1: gate input projections (both directions)
    gemm_tf32<<<dim3(G4 / 64, ROWS / 64), 128>>>(x, D_IN, Wih_f, D_IN,
        pBias, 1, pG, G4, G4, D_IN, 0);
    gemm_tf32<<<dim3(G4 / 64, ROWS / 64), 128>>>(x, D_IN, Wih_b, D_IN,
        pBias + G4, 1, pG + (size_t)ROWS * G4, G4, G4, D_IN, 0);

    // Stage 2: recurrence (both directions, all batches in parallel)
    lstm_kernel<<<NGRP * CPG, 512>>>(Whh_f, Whh_b);

    // Stage 3: head / tail projections with leaky_relu
    gemm_tf32<<<dim3(MID / 64, ROWS / 64), 128>>>(pHcat, MID, W_head, MID,
        b_head, 1, pHead, MID, MID, MID, 1);
    gemm_tf32<<<dim3(MID / 64, ROWS / 64), 128>>>(pHcat, MID, W_tail, MID,
        b_tail, 1, pTail, MID, MID, MID, 1);

    // Stage 4: biaffine projections (k=50), bias = "ones" column of W
    gemm_tf32<<<dim3(1, ROWS / 64), 128>>>(pHead, MID, W, WLD,
        W + MID, WLD, pShead, NOUT, NOUT, MID, 0);
    gemm_tf32<<<dim3(1, ROWS / 64), 128>>>(pTail, MID, W + (MID + 1), WLD,
        W + (MID + 1) + MID, WLD, pStail, NOUT, NOUT, MID, 0);

    // Stage 5: assemble 210MB output
    assemble_kernel<<<dim3(SEQ / 16, NOUT, NB), 256>>>(out);
}

// round 2
// speedup vs baseline: 1.4017x; 1.4017x over previous
#include <cuda_runtime.h>
#include <cstdint>

#define D_IN 1024
#define HID  256
#define G4   1024
#define MID  512
#define SEQ  512
#define NB   4
#define NOUT 50
#define SED  64
#define NPOS 30
#define WLD  1090           // 2*(MID+1) + SED
#define ROWS 2048           // NB*SEQ
#define CPG  8              // CTAs per recurrence group (== cluster size)
#define NGRP 8              // 2 dirs * 4 batch

// ------------------------- scratch (static device memory) -------------------
__device__ float g_G[2][ROWS][G4];      // gate input preactivations (+bias)
__device__ float g_bias[2][G4];
__device__ float g_hcat[ROWS][MID];     // [b*SEQ+t][dir*HID + j]
__device__ float g_head[ROWS][MID];
__device__ float g_tail[ROWS][MID];
__device__ float g_shead[ROWS][NOUT];   // [(b,m)][k]
__device__ float g_stail[ROWS][NOUT];   // [(b,n)][k]
__device__ float g_sztab[NOUT][NPOS];

// ------------------------- prep: bias, size table ---------------------------
__global__ void prep_kernel(const float* __restrict__ bih_f, const float* __restrict__ bhh_f,
                            const float* __restrict__ bih_b, const float* __restrict__ bhh_b,
                            const float* __restrict__ emb,   const float* __restrict__ W)
{
    int g = blockIdx.x * blockDim.x + threadIdx.x;
    if (g < G4)            g_bias[0][g]      = bih_f[g]      + bhh_f[g];
    else if (g < 2 * G4)   g_bias[1][g - G4] = bih_b[g - G4] + bhh_b[g - G4];
    if (g < NOUT * NPOS) {
        int k = g / NPOS, p = g % NPOS;
        float s = 0.f;
        #pragma unroll 8
        for (int h = 0; h < SED; h++)
            s += emb[p * SED + h] * W[k * WLD + 2 * (MID + 1) + h];
        g_sztab[k][p] = s;
    }
}

// ------------------------- tf32 GEMM: C = A @ B^T (+bias, opt leaky) --------
__device__ __forceinline__ float to_tf32(float x) {
    uint32_t u;
    asm("cvt.rna.tf32.f32 %0, %1;" : "=r"(u) : "f"(x));
    return __uint_as_float(u);
}

__global__ void __launch_bounds__(128) gemm_tf32(
    const float* __restrict__ A, int lda,
    const float* __restrict__ Bw, int ldb,
    const float* __restrict__ bias, int bstr,
    float* __restrict__ C, int ldc,
    int N, int K, int act)
{
    __shared__ float As[64][33];
    __shared__ float Bs[64][33];
    int tid  = threadIdx.x;
    int warp = tid >> 5, lane = tid & 31;
    int gq = lane >> 2, tg = lane & 3;
    int wm = (warp >> 1) * 32, wn = (warp & 1) * 32;
    int bm = blockIdx.y * 64, bn = blockIdx.x * 64;

    float acc[2][4][4];
    #pragma unroll
    for (int a = 0; a < 2; a++)
        #pragma unroll
        for (int b = 0; b < 4; b++)
            #pragma unroll
            for (int c = 0; c < 4; c++) acc[a][b][c] = 0.f;

    bool bvec = ((ldb & 3) == 0);

    for (int k0 = 0; k0 < K; k0 += 32) {
        #pragma unroll
        for (int i = 0; i < 4; i++) {
            int l4 = tid + i * 128;
            int r = l4 >> 3, c4 = (l4 & 7) << 2;
            const float4 v = *reinterpret_cast<const float4*>(A + (size_t)(bm + r) * lda + k0 + c4);
            As[r][c4 + 0] = to_tf32(v.x); As[r][c4 + 1] = to_tf32(v.y);
            As[r][c4 + 2] = to_tf32(v.z); As[r][c4 + 3] = to_tf32(v.w);
        }
        #pragma unroll
        for (int i = 0; i < 4; i++) {
            int l4 = tid + i * 128;
            int r = l4 >> 3, c4 = (l4 & 7) << 2;
            float4 v;
            if (bn + r < N) {
                if (bvec) {
                    v = *reinterpret_cast<const float4*>(Bw + (size_t)(bn + r) * ldb + k0 + c4);
                } else {
                    const float* p = Bw + (size_t)(bn + r) * ldb + k0 + c4;
                    v = make_float4(p[0], p[1], p[2], p[3]);
                }
            } else v = make_float4(0.f, 0.f, 0.f, 0.f);
            Bs[r][c4 + 0] = to_tf32(v.x); Bs[r][c4 + 1] = to_tf32(v.y);
            Bs[r][c4 + 2] = to_tf32(v.z); Bs[r][c4 + 3] = to_tf32(v.w);
        }
        __syncthreads();

        #pragma unroll
        for (int kk = 0; kk < 32; kk += 8) {
            uint32_t af[2][4], bf[4][2];
            #pragma unroll
            for (int mf = 0; mf < 2; mf++) {
                int r0 = wm + mf * 16 + gq;
                af[mf][0] = __float_as_uint(As[r0    ][kk + tg]);
                af[mf][1] = __float_as_uint(As[r0 + 8][kk + tg]);
                af[mf][2] = __float_as_uint(As[r0    ][kk + tg + 4]);
                af[mf][3] = __float_as_uint(As[r0 + 8][kk + tg + 4]);
            }
            #pragma unroll
            for (int nf = 0; nf < 4; nf++) {
                int n0 = wn + nf * 8 + gq;
                bf[nf][0] = __float_as_uint(Bs[n0][kk + tg]);
                bf[nf][1] = __float_as_uint(Bs[n0][kk + tg + 4]);
            }
            #pragma unroll
            for (int mf = 0; mf < 2; mf++)
                #pragma unroll
                for (int nf = 0; nf < 4; nf++)
                    asm volatile(
                        "mma.sync.aligned.m16n8k8.row.col.f32.tf32.tf32.f32 "
                        "{%0,%1,%2,%3}, {%4,%5,%6,%7}, {%8,%9}, {%0,%1,%2,%3};\n"
                        : "+f"(acc[mf][nf][0]), "+f"(acc[mf][nf][1]),
                          "+f"(acc[mf][nf][2]), "+f"(acc[mf][nf][3])
                        : "r"(af[mf][0]), "r"(af[mf][1]), "r"(af[mf][2]), "r"(af[mf][3]),
                          "r"(bf[nf][0]), "r"(bf[nf][1]));
        }
        __syncthreads();
    }

    #pragma unroll
    for (int mf = 0; mf < 2; mf++) {
        #pragma unroll
        for (int nf = 0; nf < 4; nf++) {
            int row = bm + wm + mf * 16 + gq;
            int col = bn + wn + nf * 8 + tg * 2;
            #pragma unroll
            for (int q = 0; q < 4; q++) {
                int r = row + (q >> 1) * 8;
                int c = col + (q & 1);
                if (c < N) {
                    float v = acc[mf][nf][q] + (bias ? bias[(size_t)c * bstr] : 0.f);
                    if (act) v = v > 0.f ? v : 0.01f * v;
                    C[(size_t)r * ldc + c] = v;
                }
            }
        }
    }
}

// ------------------------- LSTM recurrence (cluster + DSMEM) ----------------
// 8 groups (dir,batch), each = one cluster of 8 CTAs. CTA owns 32 hidden units
// (their 4 gate rows each = 128 rows of Whh). 512 threads = 32 units x 16 k-segs.
// Thread (u, seg): rows {u, 32+u, 64+u, 96+u} (i,f,g,o of unit u), k-chunks
// (seg + i*16)*4 .. +4 for i in 0..3 (interleaved for bank spread).
// h exchange: st.shared::cluster into every peer's double-buffered hs; ordering
// via barrier.cluster (arrive=release / wait=acquire).
__device__ __forceinline__ float sigm(float x) { return 1.f / (1.f + __expf(-x)); }

__device__ __forceinline__ void fma2(unsigned long long& acc,
                                     unsigned long long a, unsigned long long b) {
    asm("fma.rn.f32x2 %0, %1, %2, %0;" : "+l"(acc) : "l"(a), "l"(b));
}
__device__ __forceinline__ float pairsum(unsigned long long p) {
    uint32_t lo, hi;
    asm("mov.b64 {%0,%1}, %2;" : "=r"(lo), "=r"(hi) : "l"(p));
    return __uint_as_float(lo) + __uint_as_float(hi);
}

__global__ void __launch_bounds__(512, 1) __cluster_dims__(CPG, 1, 1)
lstm_kernel(const float* __restrict__ Whh_f, const float* __restrict__ Whh_b)
{
    __shared__ __align__(16) float hs2[2][HID];

    int grp = blockIdx.x / CPG;
    uint32_t cig;
    asm("mov.u32 %0, %%cluster_ctarank;" : "=r"(cig));
    int d = grp >> 2, b = grp & 3;
    int tid = threadIdx.x;
    int u   = tid >> 4;          // unit 0..31
    int seg = tid & 15;          // k-segment 0..15
    int j   = (int)cig * 32 + u; // global hidden unit
    const float* Whh = d ? Whh_b : Whh_f;
    const float* Gd  = &g_G[d][0][0];

    // weights: 4 gates x 4 chunks x 2 f32-pairs, packed as u64
    unsigned long long w2[4][4][2];
    #pragma unroll
    for (int gi = 0; gi < 4; gi++) {
        int grow = gi * HID + j;
        #pragma unroll
        for (int i = 0; i < 4; i++) {
            const ulonglong2 v = *reinterpret_cast<const ulonglong2*>(
                &Whh[(size_t)grow * HID + (seg + i * 16) * 4]);
            w2[gi][i][0] = v.x; w2[gi][i][1] = v.y;
        }
    }

    // zero both h buffers, then cluster-wide sync before anyone writes remotely
    if (tid < 2 * HID) ((float*)hs2)[tid] = 0.f;
    asm volatile("barrier.cluster.arrive.aligned;" ::: "memory");
    asm volatile("barrier.cluster.wait.aligned;"  ::: "memory");

    uint32_t hs_u32;
    {
        uint64_t tmp;
        asm("cvta.to.shared.u64 %0, %1;" : "=l"(tmp) : "l"((void*)hs2));
        hs_u32 = (uint32_t)tmp;
    }

    float cst = 0.f;

    for (int st = 0; st < SEQ; st++) {
        int t = d ? (SEQ - 1 - st) : st;
        int cur = st & 1, nxt = cur ^ 1;

        // preactivation input (only the seg==0 lane of each unit needs it)
        float gin[4];
        if (seg == 0) {
            size_t rbase = (size_t)(b * SEQ + t) * G4 + j;
            #pragma unroll
            for (int gi = 0; gi < 4; gi++) gin[gi] = __ldg(&Gd[rbase + gi * HID]);
        }

        // matvec: 4 gate rows of unit u over this thread's 64 k values
        unsigned long long acc[4] = {0ull, 0ull, 0ull, 0ull};
        #pragma unroll
        for (int i = 0; i < 4; i++) {
            const ulonglong2 hv = *reinterpret_cast<const ulonglong2*>(
                &hs2[cur][(seg + i * 16) * 4]);
            #pragma unroll
            for (int gi = 0; gi < 4; gi++) {
                fma2(acc[gi], w2[gi][i][0], hv.x);
                fma2(acc[gi], w2[gi][i][1], hv.y);
            }
        }
        float red[4];
        #pragma unroll
        for (int gi = 0; gi < 4; gi++) red[gi] = pairsum(acc[gi]);
        #pragma unroll
        for (int off = 8; off > 0; off >>= 1)
            #pragma unroll
            for (int gi = 0; gi < 4; gi++)
                red[gi] += __shfl_down_sync(0xffffffffu, red[gi], off, 16);

        if (seg == 0) {
            float iv = sigm (red[0] + gin[0]);
            float fv = sigm (red[1] + gin[1]);
            float gv = tanhf(red[2] + gin[2]);
            float ov = sigm (red[3] + gin[3]);
            cst = fv * cst + iv * gv;
            float h = ov * tanhf(cst);
            g_hcat[b * SEQ + t][d * HID + j] = h;
            if (st < SEQ - 1) {
                uint32_t laddr = hs_u32 + (uint32_t)(nxt * HID + j) * 4u;
                #pragma unroll
                for (int r = 0; r < CPG; r++) {
                    asm volatile(
                        "{.reg .b32 ra;\n\t"
                        "mapa.shared::cluster.u32 ra, %0, %1;\n\t"
                        "st.shared::cluster.f32 [ra], %2;}\n"
                        :: "r"(laddr), "r"(r), "f"(h) : "memory");
                }
            }
        }

        if (st < SEQ - 1) {
            asm volatile("barrier.cluster.arrive.aligned;" ::: "memory");
            asm volatile("barrier.cluster.wait.aligned;"  ::: "memory");
        }
    }
}

// ------------------------- final assembly -----------------------------------
// out[b][k][m][n] = s_head[b,k,m] + s_tail[b,k,n] + sztab[k][clamp(n-m)]
__global__ void __launch_bounds__(256) assemble_kernel(float* __restrict__ out)
{
    int b = blockIdx.z, k = blockIdx.y, m0 = blockIdx.x * 16;
    int tid = threadIdx.x;
    __shared__ float st_s[SEQ];
    __shared__ float sz_s[NPOS];
    __shared__ float sh_s[16];
    for (int i = tid; i < SEQ; i += 256) st_s[i] = g_stail[b * SEQ + i][k];
    if (tid < NPOS) sz_s[tid] = g_sztab[k][tid];
    if (tid < 16)   sh_s[tid] = g_shead[b * SEQ + m0 + tid][k];
    __syncthreads();

    float* orow = out + (((size_t)(b * NOUT + k)) * SEQ + m0) * SEQ;
    #pragma unroll
    for (int it = 0; it < 8; it++) {
        int lin = it * 256 + tid;
        int r = lin >> 7;
        int n4 = (lin & 127) << 2;
        int m = m0 + r;
        float sh = sh_s[r];
        float4 v;
        int e;
        e = min(max(n4     - m, -15), 14) + 15; v.x = sh + st_s[n4    ] + sz_s[e];
        e = min(max(n4 + 1 - m, -15), 14) + 15; v.y = sh + st_s[n4 + 1] + sz_s[e];
        e = min(max(n4 + 2 - m, -15), 14) + 15; v.z = sh + st_s[n4 + 2] + sz_s[e];
        e = min(max(n4 + 3 - m, -15), 14) + 15; v.w = sh + st_s[n4 + 3] + sz_s[e];
        *reinterpret_cast<float4*>(orow + (size_t)r * SEQ + n4) = v;
    }
}

// ------------------------- launch -------------------------------------------
extern "C" void kernel_launch(void* const* d_in, const int* in_sizes, int n_in,
                              void* d_out, int out_size)
{
    const float* x      = (const float*)d_in[0];
    const float* Wih_f  = (const float*)d_in[1];
    const float* Whh_f  = (const float*)d_in[2];
    const float* bih_f  = (const float*)d_in[3];
    const float* bhh_f  = (const float*)d_in[4];
    const float* Wih_b  = (const float*)d_in[5];
    const float* Whh_b  = (const float*)d_in[6];
    const float* bih_b  = (const float*)d_in[7];
    const float* bhh_b  = (const float*)d_in[8];
    const float* W_head = (const float*)d_in[9];
    const float* b_head = (const float*)d_in[10];
    const float* W_tail = (const float*)d_in[11];
    const float* b_tail = (const float*)d_in[12];
    const float* emb    = (const float*)d_in[13];
    const float* W      = (const float*)d_in[14];
    float* out = (float*)d_out;

    float *pG, *pBias, *pHcat, *pHead, *pTail, *pShead, *pStail;
    cudaGetSymbolAddress((void**)&pG,     g_G);
    cudaGetSymbolAddress((void**)&pBias,  g_bias);
    cudaGetSymbolAddress((void**)&pHcat,  g_hcat);
    cudaGetSymbolAddress((void**)&pHead,  g_head);
    cudaGetSymbolAddress((void**)&pTail,  g_tail);
    cudaGetSymbolAddress((void**)&pShead, g_shead);
    cudaGetSymbolAddress((void**)&pStail, g_stail);

    prep_kernel<<<8, 256>>>(bih_f, bhh_f, bih_b, bhh_b, emb, W);

    // Stage 1: gate input projections (both directions)
    gemm_tf32<<<dim3(G4 / 64, ROWS / 64), 128>>>(x, D_IN, Wih_f, D_IN,
        pBias, 1, pG, G4, G4, D_IN, 0);
    gemm_tf32<<<dim3(G4 / 64, ROWS / 64), 128>>>(x, D_IN, Wih_b, D_IN,
        pBias + G4, 1, pG + (size_t)ROWS * G4, G4, G4, D_IN, 0);

    // Stage 2: recurrence (both directions, all batches in parallel)
    lstm_kernel<<<NGRP * CPG, 512>>>(Whh_f, Whh_b);

    // Stage 3: head / tail projections with leaky_relu
    gemm_tf32<<<dim3(MID / 64, ROWS / 64), 128>>>(pHcat, MID, W_head, MID,
        b_head, 1, pHead, MID, MID, MID, 1);
    gemm_tf32<<<dim3(MID / 64, ROWS / 64), 128>>>(pHcat, MID, W_tail, MID,
        b_tail, 1, pTail, MID, MID, MID, 1);

    // Stage 4: biaffine projections (k=50), bias = "ones" column of W
    gemm_tf32<<<dim3(1, ROWS / 64), 128>>>(pHead, MID, W, WLD,
        W + MID, WLD, pShead, NOUT, NOUT, MID, 0);
    gemm_tf32<<<dim3(1, ROWS / 64), 128>>>(pTail, MID, W + (MID + 1), WLD,
        W + (MID + 1) + MID, WLD, pStail, NOUT, NOUT, MID, 0);

    // Stage 5: assemble 210MB output
    assemble_kernel<<<dim3(SEQ / 16, NOUT, NB), 256>>>(out);
}